// round 3
// baseline (speedup 1.0000x reference)
#include <cuda_runtime.h>
#include <math.h>

// Problem constants (fixed by the dataset)
#define Bc 4
#define Sc 2048
#define Ec 2048
#define Hc 16
#define Dc 128
#define MROWS (Bc*Sc)   // 8192

// Scratch buffers (device globals: allocation-free rule)
__device__ float g_Q[(size_t)Bc*Sc*Ec];
__device__ float g_K[(size_t)Bc*Sc*Ec];
__device__ float g_V[(size_t)Bc*Sc*Ec];
__device__ float g_A[(size_t)Bc*Sc*Ec];

// ---------------------------------------------------------------------------
// C[M,N] = A[M,K] @ B[N,K]^T + bias[N]     (both operands K-contiguous)
// 128x128x16 tile, 256 threads, 8x8 per thread.
// ---------------------------------------------------------------------------
__global__ __launch_bounds__(256, 2) void sgemm_nt(
    const float* __restrict__ A, const float* __restrict__ Bm,
    const float* __restrict__ bias, float* __restrict__ C,
    int M, int N, int K)
{
    __shared__ __align__(16) float As[16][132];
    __shared__ __align__(16) float Bs[16][132];

    const int tid = threadIdx.x;
    const int tx = tid & 15;
    const int ty = tid >> 4;
    const int bm = blockIdx.y * 128;
    const int bn = blockIdx.x * 128;

    float acc[8][8];
#pragma unroll
    for (int i = 0; i < 8; i++)
#pragma unroll
        for (int j = 0; j < 8; j++) acc[i][j] = 0.0f;

    for (int k0 = 0; k0 < K; k0 += 16) {
#pragma unroll
        for (int it = 0; it < 2; ++it) {
            int lin = tid + it * 256;       // 0..511
            int row = lin >> 2;             // 0..127
            int kq  = (lin & 3) << 2;       // 0,4,8,12
            float4 va = *(const float4*)(A + (size_t)(bm + row) * K + k0 + kq);
            As[kq + 0][row] = va.x; As[kq + 1][row] = va.y;
            As[kq + 2][row] = va.z; As[kq + 3][row] = va.w;
            float4 vb = *(const float4*)(Bm + (size_t)(bn + row) * K + k0 + kq);
            Bs[kq + 0][row] = vb.x; Bs[kq + 1][row] = vb.y;
            Bs[kq + 2][row] = vb.z; Bs[kq + 3][row] = vb.w;
        }
        __syncthreads();

#pragma unroll
        for (int k = 0; k < 16; k++) {
            float4 a0 = *(const float4*)&As[k][ty * 8];
            float4 a1 = *(const float4*)&As[k][ty * 8 + 4];
            float4 b0 = *(const float4*)&Bs[k][tx * 8];
            float4 b1 = *(const float4*)&Bs[k][tx * 8 + 4];
            float av[8] = {a0.x, a0.y, a0.z, a0.w, a1.x, a1.y, a1.z, a1.w};
            float bv[8] = {b0.x, b0.y, b0.z, b0.w, b1.x, b1.y, b1.z, b1.w};
#pragma unroll
            for (int i = 0; i < 8; i++)
#pragma unroll
                for (int j = 0; j < 8; j++)
                    acc[i][j] += av[i] * bv[j];
        }
        __syncthreads();
    }

    float bb[8];
    *(float4*)&bb[0] = *(const float4*)(bias + bn + tx * 8);
    *(float4*)&bb[4] = *(const float4*)(bias + bn + tx * 8 + 4);

#pragma unroll
    for (int i = 0; i < 8; i++) {
        size_t co = (size_t)(bm + ty * 8 + i) * N + bn + tx * 8;
        float4 o0 = make_float4(acc[i][0] + bb[0], acc[i][1] + bb[1],
                                acc[i][2] + bb[2], acc[i][3] + bb[3]);
        float4 o1 = make_float4(acc[i][4] + bb[4], acc[i][5] + bb[5],
                                acc[i][6] + bb[6], acc[i][7] + bb[7]);
        *(float4*)(C + co)     = o0;
        *(float4*)(C + co + 4) = o1;
    }
}

// ---------------------------------------------------------------------------
// RoPE in place on X laid out (B,S,H,D). angles: [2][S][D/2] (sin, cos).
// flag==nullptr -> always apply; else apply iff *flag != 0.
// ---------------------------------------------------------------------------
__global__ void rope_kernel(float* __restrict__ X,
                            const float* __restrict__ angles,
                            const int* __restrict__ flag)
{
    if (flag != nullptr && flag[0] == 0) return;
    int i = blockIdx.x * blockDim.x + threadIdx.x;   // over B*S*H*(D/2)
    int d  = i & 63;
    int h  = (i >> 6) & (Hc - 1);
    int bs = i >> 10;                                // b*S + s
    int s  = bs & (Sc - 1);

    float sn = angles[s * (Dc / 2) + d];
    float cs = angles[(size_t)Sc * (Dc / 2) + s * (Dc / 2) + d];

    size_t off = ((size_t)bs * Hc + h) * Dc + d;
    float x1 = X[off];
    float x2 = X[off + Dc / 2];
    X[off]          = x1 * cs - x2 * sn;
    X[off + Dc / 2] = x1 * sn + x2 * cs;
}

// ---------------------------------------------------------------------------
// Flash attention. Grid: (S/64, H, B). 256 threads, Bq=Bk=64, D=128.
// Q/K/V layout (B,S,H,D). Output written to O in same layout.
// ---------------------------------------------------------------------------
__device__ __forceinline__ float dot4(float4 a, float4 b) {
    return a.x * b.x + a.y * b.y + a.z * b.z + a.w * b.w;
}

#define ATTN_SMEM_FLOATS (3 * 64 * 128 + 64 * 65)
#define ATTN_SMEM_BYTES  (ATTN_SMEM_FLOATS * 4)

__global__ __launch_bounds__(256, 1) void attn_kernel(
    const float* __restrict__ Q, const float* __restrict__ K,
    const float* __restrict__ V, float* __restrict__ O,
    const int* __restrict__ amask, const int* __restrict__ causal_p)
{
    extern __shared__ __align__(16) float sm[];
    float* Qs = sm;               // [64][128]
    float* Ks = Qs + 64 * 128;    // [64][128]
    float* Vs = Ks + 64 * 128;    // [64][128]
    float* Ps = Vs + 64 * 128;    // [64][65]  (P^T: [kcol][row], padded)

    const int tid = threadIdx.x;
    const int tx = tid & 15;
    const int ty = tid >> 4;
    const int qt = blockIdx.x;
    const int h  = blockIdx.y;
    const int b  = blockIdx.z;
    const int causal = causal_p[0];

    const size_t base = (size_t)b * Sc * Ec + (size_t)h * Dc;
    const int q0 = qt * 64;
    const float scale = 0.08838834764831845f;   // 1/sqrt(128)
    const float NEGINF = -3.402823466e38f;

    // Load Q tile (64 x 128)
#pragma unroll
    for (int i = 0; i < 8; i++) {
        int lin = tid + i * 256;
        int row = lin >> 5;
        int c4  = (lin & 31) << 2;
        *(float4*)&Qs[row * 128 + c4] =
            *(const float4*)(Q + base + (size_t)(q0 + row) * Ec + c4);
    }

    float acc[4][8];
#pragma unroll
    for (int r = 0; r < 4; r++)
#pragma unroll
        for (int c = 0; c < 8; c++) acc[r][c] = 0.0f;

    float mrow[4], lrow[4];
#pragma unroll
    for (int r = 0; r < 4; r++) { mrow[r] = NEGINF; lrow[r] = 0.0f; }

    for (int kt = 0; kt < Sc / 64; ++kt) {
        __syncthreads();   // previous PV (reads of Vs/Ps) complete
        const int kbase = kt * 64;
#pragma unroll
        for (int i = 0; i < 8; i++) {
            int lin = tid + i * 256;
            int row = lin >> 5;
            int c4  = (lin & 31) << 2;
            *(float4*)&Ks[row * 128 + c4] =
                *(const float4*)(K + base + (size_t)(kbase + row) * Ec + c4);
            *(float4*)&Vs[row * 128 + c4] =
                *(const float4*)(V + base + (size_t)(kbase + row) * Ec + c4);
        }
        __syncthreads();

        // S = Q K^T for this tile: each thread computes 4x4
        float sacc[4][4];
#pragma unroll
        for (int r = 0; r < 4; r++)
#pragma unroll
            for (int c = 0; c < 4; c++) sacc[r][c] = 0.0f;

#pragma unroll 4
        for (int d4 = 0; d4 < 32; ++d4) {
            float4 qv[4], kv[4];
#pragma unroll
            for (int r = 0; r < 4; r++)
                qv[r] = *(const float4*)&Qs[(ty * 4 + r) * 128 + d4 * 4];
#pragma unroll
            for (int c = 0; c < 4; c++)
                kv[c] = *(const float4*)&Ks[(tx * 4 + c) * 128 + d4 * 4];
#pragma unroll
            for (int r = 0; r < 4; r++)
#pragma unroll
                for (int c = 0; c < 4; c++)
                    sacc[r][c] += dot4(qv[r], kv[c]);
        }

        // scale + mask
        int mk[4];
#pragma unroll
        for (int c = 0; c < 4; c++)
            mk[c] = amask[b * Sc + kbase + tx * 4 + c];
#pragma unroll
        for (int r = 0; r < 4; r++) {
            int qq = q0 + ty * 4 + r;
#pragma unroll
            for (int c = 0; c < 4; c++) {
                float s = sacc[r][c] * scale;
                int kk = kbase + tx * 4 + c;
                if (mk[c] == 0 || (causal && kk > qq)) s = NEGINF;
                sacc[r][c] = s;
            }
        }

        // online softmax per row (rows shared by 16 lanes: shfl width 16)
#pragma unroll
        for (int r = 0; r < 4; r++) {
            float tm = fmaxf(fmaxf(sacc[r][0], sacc[r][1]),
                             fmaxf(sacc[r][2], sacc[r][3]));
#pragma unroll
            for (int w = 8; w > 0; w >>= 1)
                tm = fmaxf(tm, __shfl_xor_sync(0xffffffffu, tm, w));
            float mnew  = fmaxf(mrow[r], tm);
            float alpha = __expf(mrow[r] - mnew);
            float ts = 0.0f;
#pragma unroll
            for (int c = 0; c < 4; c++) {
                float p = __expf(sacc[r][c] - mnew);
                sacc[r][c] = p;
                ts += p;
            }
#pragma unroll
            for (int w = 8; w > 0; w >>= 1)
                ts += __shfl_xor_sync(0xffffffffu, ts, w);
            lrow[r] = lrow[r] * alpha + ts;
            mrow[r] = mnew;
#pragma unroll
            for (int c = 0; c < 8; c++) acc[r][c] *= alpha;
        }

        // stage P (transposed, padded stride 65)
#pragma unroll
        for (int r = 0; r < 4; r++)
#pragma unroll
            for (int c = 0; c < 4; c++)
                Ps[(tx * 4 + c) * 65 + ty * 4 + r] = sacc[r][c];
        __syncthreads();

        // O += P V
#pragma unroll 4
        for (int k = 0; k < 64; k++) {
            float pr[4];
#pragma unroll
            for (int r = 0; r < 4; r++)
                pr[r] = Ps[k * 65 + ty * 4 + r];
            float4 v0 = *(const float4*)&Vs[k * 128 + tx * 8];
            float4 v1 = *(const float4*)&Vs[k * 128 + tx * 8 + 4];
#pragma unroll
            for (int r = 0; r < 4; r++) {
                float p = pr[r];
                acc[r][0] += p * v0.x; acc[r][1] += p * v0.y;
                acc[r][2] += p * v0.z; acc[r][3] += p * v0.w;
                acc[r][4] += p * v1.x; acc[r][5] += p * v1.y;
                acc[r][6] += p * v1.z; acc[r][7] += p * v1.w;
            }
        }
    }

    // normalize and store
#pragma unroll
    for (int r = 0; r < 4; r++) {
        float inv = 1.0f / lrow[r];
        size_t off = base + (size_t)(q0 + ty * 4 + r) * Ec + tx * 8;
        float4 o0 = make_float4(acc[r][0] * inv, acc[r][1] * inv,
                                acc[r][2] * inv, acc[r][3] * inv);
        float4 o1 = make_float4(acc[r][4] * inv, acc[r][5] * inv,
                                acc[r][6] * inv, acc[r][7] * inv);
        *(float4*)(O + off)     = o0;
        *(float4*)(O + off + 4) = o1;
    }
}

// ---------------------------------------------------------------------------
extern "C" void kernel_launch(void* const* d_in, const int* in_sizes, int n_in,
                              void* d_out, int out_size)
{
    const float* x_q  = (const float*)d_in[0];
    const float* x_kv = (const float*)d_in[1];
    const float* Wq   = (const float*)d_in[2];
    const float* bq   = (const float*)d_in[3];
    const float* Wk   = (const float*)d_in[4];
    const float* bk   = (const float*)d_in[5];
    const float* Wv   = (const float*)d_in[6];
    const float* bv   = (const float*)d_in[7];
    const float* Wo   = (const float*)d_in[8];
    const float* bo   = (const float*)d_in[9];
    const float* angles = (const float*)d_in[10];
    const int* amask  = (const int*)d_in[11];
    const int* causal = (const int*)d_in[12];
    const int* krope  = (const int*)d_in[13];
    float* out = (float*)d_out;

    float *Qb, *Kb, *Vb, *Ab;
    cudaGetSymbolAddress((void**)&Qb, g_Q);
    cudaGetSymbolAddress((void**)&Kb, g_K);
    cudaGetSymbolAddress((void**)&Vb, g_V);
    cudaGetSymbolAddress((void**)&Ab, g_A);

    dim3 gg(Ec / 128, MROWS / 128);   // (16, 64)

    sgemm_nt<<<gg, 256>>>(x_q,  Wq, bq, Qb, MROWS, Ec, Ec);
    sgemm_nt<<<gg, 256>>>(x_kv, Wk, bk, Kb, MROWS, Ec, Ec);
    sgemm_nt<<<gg, 256>>>(x_kv, Wv, bv, Vb, MROWS, Ec, Ec);

    int rope_threads = Bc * Sc * Hc * (Dc / 2);    // 8,388,608
    rope_kernel<<<rope_threads / 256, 256>>>(Qb, angles, (const int*)nullptr);
    rope_kernel<<<rope_threads / 256, 256>>>(Kb, angles, krope);

    cudaFuncSetAttribute(attn_kernel,
                         cudaFuncAttributeMaxDynamicSharedMemorySize,
                         ATTN_SMEM_BYTES);
    attn_kernel<<<dim3(Sc / 64, Hc, Bc), 256, ATTN_SMEM_BYTES>>>(
        Qb, Kb, Vb, Ab, amask, causal);

    sgemm_nt<<<gg, 256>>>(Ab, Wo, bo, out, MROWS, Ec, Ec);
}

// round 6
// speedup vs baseline: 1.1758x; 1.1758x over previous
#include <cuda_runtime.h>
#include <cuda_bf16.h>
#include <math.h>
#include <cstdint>

// Problem constants (fixed by the dataset)
#define Bc 4
#define Sc 2048
#define Ec 2048
#define Hc 16
#define Dc 128
#define MROWS (Bc*Sc)   // 8192

// Scratch buffers (device globals: allocation-free rule)
__device__ float g_Q[(size_t)Bc*Sc*Ec];
__device__ float g_K[(size_t)Bc*Sc*Ec];
__device__ float g_V[(size_t)Bc*Sc*Ec];
__device__ float g_A[(size_t)Bc*Sc*Ec];

// ===========================================================================
// Warp-level MMA helpers (sm_80+ PTX — compiles under compute_100)
// ===========================================================================
__device__ __forceinline__ uint32_t smem_to_u32(const void* smem_ptr) {
    uint32_t addr;
    asm("{ .reg .u64 tmp; cvta.to.shared.u64 tmp, %1; cvt.u32.u64 %0, tmp; }"
        : "=r"(addr) : "l"(smem_ptr));
    return addr;
}

__device__ __forceinline__ void ldsm_x4(uint32_t addr, uint32_t& r0, uint32_t& r1,
                                        uint32_t& r2, uint32_t& r3) {
    asm volatile("ldmatrix.sync.aligned.m8n8.x4.shared.b16 {%0,%1,%2,%3}, [%4];"
                 : "=r"(r0), "=r"(r1), "=r"(r2), "=r"(r3) : "r"(addr));
}

__device__ __forceinline__ void mma_bf16(float* d, uint32_t a0, uint32_t a1,
                                         uint32_t a2, uint32_t a3,
                                         uint32_t b0, uint32_t b1) {
    asm volatile(
        "mma.sync.aligned.m16n8k16.row.col.f32.bf16.bf16.f32 "
        "{%0,%1,%2,%3}, {%4,%5,%6,%7}, {%8,%9}, {%0,%1,%2,%3};"
        : "+f"(d[0]), "+f"(d[1]), "+f"(d[2]), "+f"(d[3])
        : "r"(a0), "r"(a1), "r"(a2), "r"(a3), "r"(b0), "r"(b1));
}

// Split fp32 -> (hi bf16, lo bf16) pairs, packed 2-wide (low 16 bits = 1st arg).
__device__ __forceinline__ void split2(float a, float b,
                                       uint32_t& hi, uint32_t& lo)
{
    uint32_t h;
    asm("cvt.rn.bf16x2.f32 %0, %1, %2;" : "=r"(h) : "f"(b), "f"(a));
    float ha = __uint_as_float(h << 16);
    float hb = __uint_as_float(h & 0xffff0000u);
    float la = a - ha;
    float lb = b - hb;
    uint32_t l;
    asm("cvt.rn.bf16x2.f32 %0, %1, %2;" : "=r"(l) : "f"(lb), "f"(la));
    hi = h; lo = l;
}

// ===========================================================================
// mma.sync GEMM:  C[M,N] = A[M,K] @ B[N,K]^T + bias[N]
// M=8192, N=K=2048 fixed. CTA tile 128x128, kt=32, split-bf16 (3 products).
// 8 warps: warp_m = wid&1 (64 rows), warp_n = wid>>1 (32 cols).
// smem: double buffer; per stage Ah|Al|Bh|Bl, each 128 rows x 40 bf16 (pad).
// ===========================================================================
#define GS_ROWB   80              // bytes per smem row (40 bf16, 32 used)
#define GS_TILE   10240           // 128 * 80
#define GS_STAGE  40960           // 4 tiles
#define GS_TOTAL  81920           // 2 stages

__device__ __forceinline__ void g_load_stage(
    const float* __restrict__ A, const float* __restrict__ Bm,
    char* buf, int bm, int bn, int k0, int tid)
{
#pragma unroll
    for (int t = 0; t < 4; ++t) {
        int c   = tid + t * 256;       // 0..1023
        int row = c >> 3;              // 0..127
        int col = c & 7;               // float4 index (8 per 32-float row)
        float4 v = *(const float4*)(A + (size_t)(bm + row) * 2048 + k0 + (col << 2));
        uint32_t h0, l0, h1, l1;
        split2(v.x, v.y, h0, l0);
        split2(v.z, v.w, h1, l1);
        int off = row * GS_ROWB + col * 8;
        *(uint2*)(buf + off)           = make_uint2(h0, h1);
        *(uint2*)(buf + GS_TILE + off) = make_uint2(l0, l1);
    }
#pragma unroll
    for (int t = 0; t < 4; ++t) {
        int c   = tid + t * 256;
        int row = c >> 3;
        int col = c & 7;
        float4 v = *(const float4*)(Bm + (size_t)(bn + row) * 2048 + k0 + (col << 2));
        uint32_t h0, l0, h1, l1;
        split2(v.x, v.y, h0, l0);
        split2(v.z, v.w, h1, l1);
        int off = row * GS_ROWB + col * 8;
        *(uint2*)(buf + 2 * GS_TILE + off) = make_uint2(h0, h1);
        *(uint2*)(buf + 3 * GS_TILE + off) = make_uint2(l0, l1);
    }
}

__global__ __launch_bounds__(256, 1) void gemm_mma(
    const float* __restrict__ A, const float* __restrict__ Bm,
    const float* __restrict__ bias, float* __restrict__ C)
{
    extern __shared__ char smem[];
    const uint32_t smem_base = smem_to_u32(smem);
    const int tid = threadIdx.x;
    const int wid = tid >> 5;
    const int lane = tid & 31;
    const int bm = blockIdx.y * 128;
    const int bn = blockIdx.x * 128;

    const int warp_m = (wid & 1) * 64;   // 64-row warp tile
    const int warp_n = (wid >> 1) * 32;  // 32-col warp tile

    // Per-lane ldmatrix address offsets (constant across stages):
    // A x4 at (m0,k0): quadrants: q&1 -> m halves, q>>1 -> k halves.
    const int q  = lane >> 3;
    const int ri = lane & 7;
    int a_off[4], b_off[2];
#pragma unroll
    for (int mt = 0; mt < 4; ++mt)
        a_off[mt] = (warp_m + mt * 16 + (q & 1) * 8 + ri) * GS_ROWB + (q >> 1) * 16;
#pragma unroll
    for (int np = 0; np < 2; ++np)
        b_off[np] = (warp_n + np * 16 + (q >> 1) * 8 + ri) * GS_ROWB + (q & 1) * 16;

    float d[4][4][4];
#pragma unroll
    for (int i = 0; i < 4; i++)
#pragma unroll
        for (int j = 0; j < 4; j++)
#pragma unroll
            for (int e = 0; e < 4; e++) d[i][j][e] = 0.0f;

    g_load_stage(A, Bm, smem, bm, bn, 0, tid);
    __syncthreads();

    const int NSTAGES = 2048 / 32;     // 64
    for (int s = 0; s < NSTAGES; ++s) {
        if (s + 1 < NSTAGES)
            g_load_stage(A, Bm, smem + ((s + 1) & 1) * GS_STAGE,
                         bm, bn, (s + 1) * 32, tid);

        const uint32_t sb = smem_base + (s & 1) * GS_STAGE;
#pragma unroll
        for (int ks = 0; ks < 2; ++ks) {
            const int kb = ks * 32;    // k offset in bytes (16 bf16)

            // B fragments (hi & lo) for 4 n-tiles (2 x4 loads each)
            uint32_t bh[4][2], bl[4][2];
#pragma unroll
            for (int np = 0; np < 2; ++np) {
                ldsm_x4(sb + 2 * GS_TILE + b_off[np] + kb,
                        bh[np * 2][0], bh[np * 2][1], bh[np * 2 + 1][0], bh[np * 2 + 1][1]);
                ldsm_x4(sb + 3 * GS_TILE + b_off[np] + kb,
                        bl[np * 2][0], bl[np * 2][1], bl[np * 2 + 1][0], bl[np * 2 + 1][1]);
            }

#pragma unroll
            for (int mt = 0; mt < 4; ++mt) {
                uint32_t ah0, ah1, ah2, ah3, al0, al1, al2, al3;
                ldsm_x4(sb + a_off[mt] + kb, ah0, ah1, ah2, ah3);
                ldsm_x4(sb + GS_TILE + a_off[mt] + kb, al0, al1, al2, al3);
#pragma unroll
                for (int nt = 0; nt < 4; ++nt) {
                    mma_bf16(d[mt][nt], ah0, ah1, ah2, ah3, bh[nt][0], bh[nt][1]);
                    mma_bf16(d[mt][nt], ah0, ah1, ah2, ah3, bl[nt][0], bl[nt][1]);
                    mma_bf16(d[mt][nt], al0, al1, al2, al3, bh[nt][0], bh[nt][1]);
                }
            }
        }
        __syncthreads();
    }

    // Epilogue: direct stores with bias (fragment layout, float2 per half)
    const int col_in = (lane & 3) * 2;
    const int row_in = lane >> 2;
#pragma unroll
    for (int mt = 0; mt < 4; ++mt) {
#pragma unroll
        for (int nt = 0; nt < 4; ++nt) {
            int gc = bn + warp_n + nt * 8 + col_in;
            float b0 = bias[gc], b1 = bias[gc + 1];
            int gr0 = bm + warp_m + mt * 16 + row_in;
            *(float2*)(C + (size_t)gr0 * 2048 + gc) =
                make_float2(d[mt][nt][0] + b0, d[mt][nt][1] + b1);
            *(float2*)(C + (size_t)(gr0 + 8) * 2048 + gc) =
                make_float2(d[mt][nt][2] + b0, d[mt][nt][3] + b1);
        }
    }
}

// ---------------------------------------------------------------------------
// RoPE in place on X laid out (B,S,H,D). angles: [2][S][D/2] (sin, cos).
// flag==nullptr -> always apply; else apply iff *flag != 0.
// ---------------------------------------------------------------------------
__global__ void rope_kernel(float* __restrict__ X,
                            const float* __restrict__ angles,
                            const int* __restrict__ flag)
{
    if (flag != nullptr && flag[0] == 0) return;
    int i = blockIdx.x * blockDim.x + threadIdx.x;   // over B*S*H*(D/2)
    int d  = i & 63;
    int h  = (i >> 6) & (Hc - 1);
    int bs = i >> 10;                                // b*S + s
    int s  = bs & (Sc - 1);

    float sn = angles[s * (Dc / 2) + d];
    float cs = angles[(size_t)Sc * (Dc / 2) + s * (Dc / 2) + d];

    size_t off = ((size_t)bs * Hc + h) * Dc + d;
    float x1 = X[off];
    float x2 = X[off + Dc / 2];
    X[off]          = x1 * cs - x2 * sn;
    X[off + Dc / 2] = x1 * sn + x2 * cs;
}

// ---------------------------------------------------------------------------
// Flash attention. Grid: (S/64, H, B). 256 threads, Bq=Bk=64, D=128.
// Q/K/V layout (B,S,H,D). Output written to O in same layout.
// ---------------------------------------------------------------------------
__device__ __forceinline__ float dot4(float4 a, float4 b) {
    return a.x * b.x + a.y * b.y + a.z * b.z + a.w * b.w;
}

#define ATTN_SMEM_FLOATS (3 * 64 * 128 + 64 * 65)
#define ATTN_SMEM_BYTES  (ATTN_SMEM_FLOATS * 4)

__global__ __launch_bounds__(256, 1) void attn_kernel(
    const float* __restrict__ Q, const float* __restrict__ K,
    const float* __restrict__ V, float* __restrict__ O,
    const int* __restrict__ amask, const int* __restrict__ causal_p)
{
    extern __shared__ __align__(16) float sm[];
    float* Qs = sm;               // [64][128]
    float* Ks = Qs + 64 * 128;    // [64][128]
    float* Vs = Ks + 64 * 128;    // [64][128]
    float* Ps = Vs + 64 * 128;    // [64][65]  (P^T: [kcol][row], padded)

    const int tid = threadIdx.x;
    const int tx = tid & 15;
    const int ty = tid >> 4;
    const int qt = blockIdx.x;
    const int h  = blockIdx.y;
    const int b  = blockIdx.z;
    const int causal = causal_p[0];

    const size_t base = (size_t)b * Sc * Ec + (size_t)h * Dc;
    const int q0 = qt * 64;
    const float scale = 0.08838834764831845f;   // 1/sqrt(128)
    const float NEGINF = -3.402823466e38f;

    // Load Q tile (64 x 128)
#pragma unroll
    for (int i = 0; i < 8; i++) {
        int lin = tid + i * 256;
        int row = lin >> 5;
        int c4  = (lin & 31) << 2;
        *(float4*)&Qs[row * 128 + c4] =
            *(const float4*)(Q + base + (size_t)(q0 + row) * Ec + c4);
    }

    float acc[4][8];
#pragma unroll
    for (int r = 0; r < 4; r++)
#pragma unroll
        for (int c = 0; c < 8; c++) acc[r][c] = 0.0f;

    float mrow[4], lrow[4];
#pragma unroll
    for (int r = 0; r < 4; r++) { mrow[r] = NEGINF; lrow[r] = 0.0f; }

    for (int kt = 0; kt < Sc / 64; ++kt) {
        __syncthreads();   // previous PV (reads of Vs/Ps) complete
        const int kbase = kt * 64;
#pragma unroll
        for (int i = 0; i < 8; i++) {
            int lin = tid + i * 256;
            int row = lin >> 5;
            int c4  = (lin & 31) << 2;
            *(float4*)&Ks[row * 128 + c4] =
                *(const float4*)(K + base + (size_t)(kbase + row) * Ec + c4);
            *(float4*)&Vs[row * 128 + c4] =
                *(const float4*)(V + base + (size_t)(kbase + row) * Ec + c4);
        }
        __syncthreads();

        // S = Q K^T for this tile: each thread computes 4x4
        float sacc[4][4];
#pragma unroll
        for (int r = 0; r < 4; r++)
#pragma unroll
            for (int c = 0; c < 4; c++) sacc[r][c] = 0.0f;

#pragma unroll 4
        for (int d4 = 0; d4 < 32; ++d4) {
            float4 qv[4], kv[4];
#pragma unroll
            for (int r = 0; r < 4; r++)
                qv[r] = *(const float4*)&Qs[(ty * 4 + r) * 128 + d4 * 4];
#pragma unroll
            for (int c = 0; c < 4; c++)
                kv[c] = *(const float4*)&Ks[(tx * 4 + c) * 128 + d4 * 4];
#pragma unroll
            for (int r = 0; r < 4; r++)
#pragma unroll
                for (int c = 0; c < 4; c++)
                    sacc[r][c] += dot4(qv[r], kv[c]);
        }

        // scale + mask
        int mk[4];
#pragma unroll
        for (int c = 0; c < 4; c++)
            mk[c] = amask[b * Sc + kbase + tx * 4 + c];
#pragma unroll
        for (int r = 0; r < 4; r++) {
            int qq = q0 + ty * 4 + r;
#pragma unroll
            for (int c = 0; c < 4; c++) {
                float s = sacc[r][c] * scale;
                int kk = kbase + tx * 4 + c;
                if (mk[c] == 0 || (causal && kk > qq)) s = NEGINF;
                sacc[r][c] = s;
            }
        }

        // online softmax per row (rows shared by 16 lanes: shfl width 16)
#pragma unroll
        for (int r = 0; r < 4; r++) {
            float tm = fmaxf(fmaxf(sacc[r][0], sacc[r][1]),
                             fmaxf(sacc[r][2], sacc[r][3]));
#pragma unroll
            for (int w = 8; w > 0; w >>= 1)
                tm = fmaxf(tm, __shfl_xor_sync(0xffffffffu, tm, w));
            float mnew  = fmaxf(mrow[r], tm);
            float alpha = __expf(mrow[r] - mnew);
            float ts = 0.0f;
#pragma unroll
            for (int c = 0; c < 4; c++) {
                float p = __expf(sacc[r][c] - mnew);
                sacc[r][c] = p;
                ts += p;
            }
#pragma unroll
            for (int w = 8; w > 0; w >>= 1)
                ts += __shfl_xor_sync(0xffffffffu, ts, w);
            lrow[r] = lrow[r] * alpha + ts;
            mrow[r] = mnew;
#pragma unroll
            for (int c = 0; c < 8; c++) acc[r][c] *= alpha;
        }

        // stage P (transposed, padded stride 65)
#pragma unroll
        for (int r = 0; r < 4; r++)
#pragma unroll
            for (int c = 0; c < 4; c++)
                Ps[(tx * 4 + c) * 65 + ty * 4 + r] = sacc[r][c];
        __syncthreads();

        // O += P V
#pragma unroll 4
        for (int k = 0; k < 64; k++) {
            float pr[4];
#pragma unroll
            for (int r = 0; r < 4; r++)
                pr[r] = Ps[k * 65 + ty * 4 + r];
            float4 v0 = *(const float4*)&Vs[k * 128 + tx * 8];
            float4 v1 = *(const float4*)&Vs[k * 128 + tx * 8 + 4];
#pragma unroll
            for (int r = 0; r < 4; r++) {
                float p = pr[r];
                acc[r][0] += p * v0.x; acc[r][1] += p * v0.y;
                acc[r][2] += p * v0.z; acc[r][3] += p * v0.w;
                acc[r][4] += p * v1.x; acc[r][5] += p * v1.y;
                acc[r][6] += p * v1.z; acc[r][7] += p * v1.w;
            }
        }
    }

    // normalize and store
#pragma unroll
    for (int r = 0; r < 4; r++) {
        float inv = 1.0f / lrow[r];
        size_t off = base + (size_t)(q0 + ty * 4 + r) * Ec + tx * 8;
        float4 o0 = make_float4(acc[r][0] * inv, acc[r][1] * inv,
                                acc[r][2] * inv, acc[r][3] * inv);
        float4 o1 = make_float4(acc[r][4] * inv, acc[r][5] * inv,
                                acc[r][6] * inv, acc[r][7] * inv);
        *(float4*)(O + off)     = o0;
        *(float4*)(O + off + 4) = o1;
    }
}

// ---------------------------------------------------------------------------
extern "C" void kernel_launch(void* const* d_in, const int* in_sizes, int n_in,
                              void* d_out, int out_size)
{
    const float* x_q  = (const float*)d_in[0];
    const float* x_kv = (const float*)d_in[1];
    const float* Wq   = (const float*)d_in[2];
    const float* bq   = (const float*)d_in[3];
    const float* Wk   = (const float*)d_in[4];
    const float* bk   = (const float*)d_in[5];
    const float* Wv   = (const float*)d_in[6];
    const float* bv   = (const float*)d_in[7];
    const float* Wo   = (const float*)d_in[8];
    const float* bo   = (const float*)d_in[9];
    const float* angles = (const float*)d_in[10];
    const int* amask  = (const int*)d_in[11];
    const int* causal = (const int*)d_in[12];
    const int* krope  = (const int*)d_in[13];
    float* out = (float*)d_out;

    float *Qb, *Kb, *Vb, *Ab;
    cudaGetSymbolAddress((void**)&Qb, g_Q);
    cudaGetSymbolAddress((void**)&Kb, g_K);
    cudaGetSymbolAddress((void**)&Vb, g_V);
    cudaGetSymbolAddress((void**)&Ab, g_A);

    cudaFuncSetAttribute(gemm_mma,
                         cudaFuncAttributeMaxDynamicSharedMemorySize,
                         GS_TOTAL);

    dim3 gg(Ec / 128, MROWS / 128);   // (16, 64)

    gemm_mma<<<gg, 256, GS_TOTAL>>>(x_q,  Wq, bq, Qb);
    gemm_mma<<<gg, 256, GS_TOTAL>>>(x_kv, Wk, bk, Kb);
    gemm_mma<<<gg, 256, GS_TOTAL>>>(x_kv, Wv, bv, Vb);

    int rope_threads = Bc * Sc * Hc * (Dc / 2);    // 8,388,608
    rope_kernel<<<rope_threads / 256, 256>>>(Qb, angles, (const int*)nullptr);
    rope_kernel<<<rope_threads / 256, 256>>>(Kb, angles, krope);

    cudaFuncSetAttribute(attn_kernel,
                         cudaFuncAttributeMaxDynamicSharedMemorySize,
                         ATTN_SMEM_BYTES);
    attn_kernel<<<dim3(Sc / 64, Hc, Bc), 256, ATTN_SMEM_BYTES>>>(
        Qb, Kb, Vb, Ab, amask, causal);

    gemm_mma<<<gg, 256, GS_TOTAL>>>(Ab, Wo, bo, out);
}